// round 13
// baseline (speedup 1.0000x reference)
#include <cuda_runtime.h>
#include <cuda_bf16.h>
#include <cstdint>

#define Bq 4
#define Vq 50000
#define Cq 160
#define V_CTA 128         // vertices per CTA (4 warps x m32)
#define NTHR 128
#define KS 10             // 160 / 16
#define NT 6              // 48 / 8
#define SB_U32 (KS * NT * 32 * 4)     // B frags in gmem (u32 count)
#define STAGES 5
#define CHUNK 8192                    // 128 rows x 64B per kstep
#define SMEM_BYTES (STAGES * CHUNK)   // 40960; D scratch (25088B) aliases

// B operand fragments in gmem: u32 [ks][nt][lane][4] = (bhi0,bhi1,blo0,blo1)
// k-permutation: thread t of the mma owns ACTUAL k = ks*16 + 4t .. 4t+3.
__device__ __align__(16) unsigned int g_bfrag[SB_U32];

// ---------------- Precompute: G -> permuted .col B fragments (bf16 hi/lo) ---
__global__ void precompute_kernel(const float* __restrict__ X,
                                  const float* __restrict__ Vn,
                                  const float* __restrict__ r6,
                                  const int* __restrict__ idx) {
    int i = blockIdx.x * blockDim.x + threadIdx.x;
    if (i >= Bq * Cq) return;
    int b = i / Cq, c = i % Cq;

    const float* d6 = r6 + (size_t)(b * Cq + c) * 6;
    float a1x = d6[0], a1y = d6[1], a1z = d6[2];
    float a2x = d6[3], a2y = d6[4], a2z = d6[5];

    float n1 = fmaxf(sqrtf(a1x*a1x + a1y*a1y + a1z*a1z), 1e-8f);
    float b1x = a1x/n1, b1y = a1y/n1, b1z = a1z/n1;
    float dt = b1x*a2x + b1y*a2y + b1z*a2z;
    float px = a2x - dt*b1x, py = a2y - dt*b1y, pz = a2z - dt*b1z;
    float n2 = fmaxf(sqrtf(px*px + py*py + pz*pz), 1e-8f);
    float b2x = px/n2, b2y = py/n2, b2z = pz/n2;
    float b3x = b1y*b2z - b1z*b2y;
    float b3y = b1z*b2x - b1x*b2z;
    float b3z = b1x*b2y - b1y*b2x;

    float R[3][3] = {{b1x,b1y,b1z},{b2x,b2y,b2z},{b3x,b3y,b3z}};

    int vi = idx[c];
    vi = max(0, min(Vq - 1, vi));
    const float* xc = X + ((size_t)b * Vq + vi) * 3;
    float cen[3] = {xc[0], xc[1], xc[2]};
    const float* vn = Vn + (size_t)(b * Cq + c) * 3;

    float g[12];
    #pragma unroll
    for (int k = 0; k < 3; k++) {
        #pragma unroll
        for (int d = 0; d < 3; d++) g[k*3 + d] = R[k][d];
        g[9 + k] = cen[k] + vn[k]
                 - (R[k][0]*cen[0] + R[k][1]*cen[1] + R[k][2]*cen[2]);
    }

    int ks  = c >> 4, klo = c & 15;
    int t   = klo >> 2;
    int j   = klo & 3;
    int reg = j >> 1;
    int elem = j & 1;
    unsigned short* p16 = (unsigned short*)g_bfrag;

    #pragma unroll
    for (int jj = 0; jj < 12; jj++) {
        int n = jj * 4 + b;
        int lane = (n & 7) * 4 + t;
        int slot = ((ks * NT + (n >> 3)) * 32 + lane) * 4;
        __nv_bfloat16 hi = __float2bfloat16_rn(g[jj]);
        __nv_bfloat16 lo = __float2bfloat16_rn(g[jj] - __bfloat162float(hi));
        p16[(slot + reg)     * 2 + elem] = __bfloat16_as_ushort(hi);
        p16[(slot + 2 + reg) * 2 + elem] = __bfloat16_as_ushort(lo);
    }
}

// ---------------- helpers ----------------
__device__ __forceinline__ uint32_t pack_bf16x2(float lo, float hi) {
    uint32_t r;
    asm("cvt.rn.bf16x2.f32 %0, %1, %2;" : "=r"(r) : "f"(hi), "f"(lo));
    return r;
}
__device__ __forceinline__ void mma16816(float* d, const uint32_t* a,
                                         uint32_t b0, uint32_t b1) {
    asm("mma.sync.aligned.m16n8k16.row.col.f32.bf16.bf16.f32 "
        "{%0,%1,%2,%3}, {%4,%5,%6,%7}, {%8,%9}, {%0,%1,%2,%3};"
        : "+f"(d[0]), "+f"(d[1]), "+f"(d[2]), "+f"(d[3])
        : "r"(a[0]), "r"(a[1]), "r"(a[2]), "r"(a[3]), "r"(b0), "r"(b1));
}
__device__ __forceinline__ void split4(float4 w, uint32_t& h01, uint32_t& h23,
                                       uint32_t& l01, uint32_t& l23) {
    h01 = pack_bf16x2(w.x, w.y);
    float hx = __uint_as_float(h01 << 16);
    float hy = __uint_as_float(h01 & 0xFFFF0000u);
    l01 = pack_bf16x2(w.x - hx, w.y - hy);
    h23 = pack_bf16x2(w.z, w.w);
    float hz = __uint_as_float(h23 << 16);
    float hw = __uint_as_float(h23 & 0xFFFF0000u);
    l23 = pack_bf16x2(w.z - hz, w.w - hw);
}
#define CP16(dst, src) \
    asm volatile("cp.async.cg.shared.global [%0], [%1], 16;" \
                 :: "r"(dst), "l"(src) : "memory")
#define CP_COMMIT() asm volatile("cp.async.commit_group;" ::: "memory")
#define CP_WAIT4()  asm volatile("cp.async.wait_group 4;" ::: "memory")
#define CP_WAIT0()  asm volatile("cp.async.wait_group 0;" ::: "memory")

// ---------------- Main kernel: m32/warp, cp.async W ring, B via __ldg -------
__global__ void __launch_bounds__(NTHR, 3)
main_kernel(const float* __restrict__ W,
            const float* __restrict__ X,
            float* __restrict__ out) {
    extern __shared__ __align__(16) unsigned int smem[];

    int tid = threadIdx.x, wid = tid >> 5, lane = tid & 31;
    int g = lane >> 2, t = lane & 3;
    int vbase = blockIdx.x * V_CTA;

    // 4 fragment row-groups per warp: g, g+8 (tile0), g+16, g+24 (tile1)
    const float* wp[4];
    #pragma unroll
    for (int i = 0; i < 4; i++) {
        int r = min(vbase + wid * 32 + g + 8 * i, Vq - 1);
        wp[i] = W + (size_t)r * Cq + 4 * t;
    }

    // ring: stage s holds kstep chunk; thread owns 4x16B, self-produced
    uint32_t ring = (uint32_t)__cvta_generic_to_shared(smem);
    uint32_t myoff = (uint32_t)((wid * 32 + g) * 64 + t * 16);

    // prologue: fill all 5 stages (ksteps 0..4), one group per stage
    #pragma unroll
    for (int ks = 0; ks < STAGES; ks++) {
        uint32_t dst = ring + ks * CHUNK + myoff;
        CP16(dst,        wp[0] + ks * 16);
        CP16(dst + 512,  wp[1] + ks * 16);
        CP16(dst + 1024, wp[2] + ks * 16);
        CP16(dst + 1536, wp[3] + ks * 16);
        CP_COMMIT();
    }

    float d0[NT][4], d1[NT][4];
    #pragma unroll
    for (int nt = 0; nt < NT; nt++)
        #pragma unroll
        for (int r = 0; r < 4; r++) { d0[nt][r] = 0.0f; d1[nt][r] = 0.0f; }

    const char* smem_c = (const char*)smem;

    #pragma unroll
    for (int ks = 0; ks < KS; ks++) {
        CP_WAIT4();   // oldest group (stage for kstep ks) complete
        const float4* a = (const float4*)(smem_c + (ks % STAGES) * CHUNK + myoff);
        float4 wa0 = a[0];
        float4 wa1 = a[32];
        float4 wa2 = a[64];
        float4 wa3 = a[96];

        // refill stage with kstep ks+5; always commit to keep group count
        if (ks + STAGES < KS) {
            uint32_t dst = ring + (ks % STAGES) * CHUNK + myoff;
            CP16(dst,        wp[0] + (ks + STAGES) * 16);
            CP16(dst + 512,  wp[1] + (ks + STAGES) * 16);
            CP16(dst + 1024, wp[2] + (ks + STAGES) * 16);
            CP16(dst + 1536, wp[3] + (ks + STAGES) * 16);
        }
        CP_COMMIT();

        uint32_t ah0[4], al0[4], ah1[4], al1[4];
        split4(wa0, ah0[0], ah0[2], al0[0], al0[2]);
        split4(wa1, ah0[1], ah0[3], al0[1], al0[3]);
        split4(wa2, ah1[0], ah1[2], al1[0], al1[2]);
        split4(wa3, ah1[1], ah1[3], al1[1], al1[3]);

        // B fragments straight from gmem (L1-resident after first touch)
        uint4 bb[NT];
        #pragma unroll
        for (int nt = 0; nt < NT; nt++)
            bb[nt] = __ldg((const uint4*)&g_bfrag[((ks * NT + nt) * 32 + lane) * 4]);

        #pragma unroll
        for (int nt = 0; nt < NT; nt++) {          // pass 0: hi*hi
            mma16816(d0[nt], ah0, bb[nt].x, bb[nt].y);
            mma16816(d1[nt], ah1, bb[nt].x, bb[nt].y);
        }
        #pragma unroll
        for (int nt = 0; nt < NT; nt++) {          // pass 1: hi*lo
            mma16816(d0[nt], ah0, bb[nt].z, bb[nt].w);
            mma16816(d1[nt], ah1, bb[nt].z, bb[nt].w);
        }
        #pragma unroll
        for (int nt = 0; nt < NT; nt++) {          // pass 2: lo*hi
            mma16816(d0[nt], al0, bb[nt].x, bb[nt].y);
            mma16816(d1[nt], al1, bb[nt].x, bb[nt].y);
        }
    }

    CP_WAIT0();
    __syncthreads();   // ring dead; alias as D scratch [128][49]
    float* Dsm = (float*)smem;
    #pragma unroll
    for (int nt = 0; nt < NT; nt++) {
        int col = nt * 8 + 2 * t;
        int q0 = (wid * 32 + g) * 49;
        int q1 = (wid * 32 + g + 8) * 49;
        int q2 = (wid * 32 + g + 16) * 49;
        int q3 = (wid * 32 + g + 24) * 49;
        Dsm[q0 + col] = d0[nt][0]; Dsm[q0 + col + 1] = d0[nt][1];
        Dsm[q1 + col] = d0[nt][2]; Dsm[q1 + col + 1] = d0[nt][3];
        Dsm[q2 + col] = d1[nt][0]; Dsm[q2 + col + 1] = d1[nt][1];
        Dsm[q3 + col] = d1[nt][2]; Dsm[q3 + col + 1] = d1[nt][3];
    }
    __syncthreads();

    // Epilogue: thread tid owns vertex vbase+tid, all 4 batches
    int v = vbase + tid;
    if (v < Vq) {
        float m[12];
        #pragma unroll
        for (int b = 0; b < Bq; b++) {
            #pragma unroll
            for (int j = 0; j < 12; j++) m[j] = Dsm[tid * 49 + j * 4 + b];
            const float* xp = X + ((size_t)b * Vq + v) * 3;
            float x0 = xp[0], x1 = xp[1], x2 = xp[2];
            float* op = out + ((size_t)b * Vq + v) * 3;
            op[0] = m[9]  + m[0]*x0 + m[1]*x1 + m[2]*x2;
            op[1] = m[10] + m[3]*x0 + m[4]*x1 + m[5]*x2;
            op[2] = m[11] + m[6]*x0 + m[7]*x1 + m[8]*x2;
        }
    }
}

// ---------------- launch ----------------
extern "C" void kernel_launch(void* const* d_in, const int* in_sizes, int n_in,
                              void* d_out, int out_size) {
    const float* X   = (const float*)d_in[0];
    const float* Vn  = (const float*)d_in[1];
    const float* r6  = (const float*)d_in[2];
    const float* W   = (const float*)d_in[3];
    const int*   idx = (const int*)d_in[4];   // JAX x64-disabled: int64 -> int32
    float* out = (float*)d_out;

    precompute_kernel<<<(Bq * Cq + 127) / 128, 128>>>(X, Vn, r6, idx);

    cudaFuncSetAttribute(main_kernel,
                         cudaFuncAttributeMaxDynamicSharedMemorySize, SMEM_BYTES);
    int grid = (Vq + V_CTA - 1) / V_CTA;    // 391
    main_kernel<<<grid, NTHR, SMEM_BYTES>>>(W, X, out);
}

// round 14
// speedup vs baseline: 1.3607x; 1.3607x over previous
#include <cuda_runtime.h>
#include <cuda_bf16.h>
#include <cstdint>

#define Bq 4
#define Vq 50000
#define Cq 160
#define V_CTA 128         // vertices per CTA (4 warps x m32)
#define NTHR 128
#define KS 10             // 160 / 16
#define NT 6              // 48 / 8
#define SB_U32 (KS * NT * 32 * 4)     // 7680 u32 = 30720B (B frags)
#define RING_OFF 30720
#define STAGES 5
#define CHUNK 8192                    // 128 rows x 64B per kstep
#define SMEM_BYTES (RING_OFF + STAGES * CHUNK)   // 71680

// B operand fragments in gmem: u32 [ks][nt][lane][4] = (bhi0,bhi1,blo0,blo1)
// k-permutation: thread t of the mma owns ACTUAL k = ks*16 + 4t .. 4t+3.
__device__ __align__(16) unsigned int g_bfrag[SB_U32];

// ---------------- Precompute: G -> permuted .col B fragments (bf16 hi/lo) ---
__global__ void precompute_kernel(const float* __restrict__ X,
                                  const float* __restrict__ Vn,
                                  const float* __restrict__ r6,
                                  const int* __restrict__ idx) {
    int i = blockIdx.x * blockDim.x + threadIdx.x;
    if (i >= Bq * Cq) return;
    int b = i / Cq, c = i % Cq;

    const float* d6 = r6 + (size_t)(b * Cq + c) * 6;
    float a1x = d6[0], a1y = d6[1], a1z = d6[2];
    float a2x = d6[3], a2y = d6[4], a2z = d6[5];

    float n1 = fmaxf(sqrtf(a1x*a1x + a1y*a1y + a1z*a1z), 1e-8f);
    float b1x = a1x/n1, b1y = a1y/n1, b1z = a1z/n1;
    float dt = b1x*a2x + b1y*a2y + b1z*a2z;
    float px = a2x - dt*b1x, py = a2y - dt*b1y, pz = a2z - dt*b1z;
    float n2 = fmaxf(sqrtf(px*px + py*py + pz*pz), 1e-8f);
    float b2x = px/n2, b2y = py/n2, b2z = pz/n2;
    float b3x = b1y*b2z - b1z*b2y;
    float b3y = b1z*b2x - b1x*b2z;
    float b3z = b1x*b2y - b1y*b2x;

    float R[3][3] = {{b1x,b1y,b1z},{b2x,b2y,b2z},{b3x,b3y,b3z}};

    int vi = idx[c];
    vi = max(0, min(Vq - 1, vi));
    const float* xc = X + ((size_t)b * Vq + vi) * 3;
    float cen[3] = {xc[0], xc[1], xc[2]};
    const float* vn = Vn + (size_t)(b * Cq + c) * 3;

    float g[12];
    #pragma unroll
    for (int k = 0; k < 3; k++) {
        #pragma unroll
        for (int d = 0; d < 3; d++) g[k*3 + d] = R[k][d];
        g[9 + k] = cen[k] + vn[k]
                 - (R[k][0]*cen[0] + R[k][1]*cen[1] + R[k][2]*cen[2]);
    }

    int ks  = c >> 4, klo = c & 15;
    int t   = klo >> 2;
    int j   = klo & 3;
    int reg = j >> 1;
    int elem = j & 1;
    unsigned short* p16 = (unsigned short*)g_bfrag;

    #pragma unroll
    for (int jj = 0; jj < 12; jj++) {
        int n = jj * 4 + b;
        int lane = (n & 7) * 4 + t;
        int slot = ((ks * NT + (n >> 3)) * 32 + lane) * 4;
        __nv_bfloat16 hi = __float2bfloat16_rn(g[jj]);
        __nv_bfloat16 lo = __float2bfloat16_rn(g[jj] - __bfloat162float(hi));
        p16[(slot + reg)     * 2 + elem] = __bfloat16_as_ushort(hi);
        p16[(slot + 2 + reg) * 2 + elem] = __bfloat16_as_ushort(lo);
    }
}

// ---------------- helpers ----------------
__device__ __forceinline__ uint32_t pack_bf16x2(float lo, float hi) {
    uint32_t r;
    asm("cvt.rn.bf16x2.f32 %0, %1, %2;" : "=r"(r) : "f"(hi), "f"(lo));
    return r;
}
__device__ __forceinline__ void mma16816(float* d, const uint32_t* a,
                                         uint32_t b0, uint32_t b1) {
    asm("mma.sync.aligned.m16n8k16.row.col.f32.bf16.bf16.f32 "
        "{%0,%1,%2,%3}, {%4,%5,%6,%7}, {%8,%9}, {%0,%1,%2,%3};"
        : "+f"(d[0]), "+f"(d[1]), "+f"(d[2]), "+f"(d[3])
        : "r"(a[0]), "r"(a[1]), "r"(a[2]), "r"(a[3]), "r"(b0), "r"(b1));
}
__device__ __forceinline__ void split4(float4 w, uint32_t& h01, uint32_t& h23,
                                       uint32_t& l01, uint32_t& l23) {
    h01 = pack_bf16x2(w.x, w.y);
    float hx = __uint_as_float(h01 << 16);
    float hy = __uint_as_float(h01 & 0xFFFF0000u);
    l01 = pack_bf16x2(w.x - hx, w.y - hy);
    h23 = pack_bf16x2(w.z, w.w);
    float hz = __uint_as_float(h23 << 16);
    float hw = __uint_as_float(h23 & 0xFFFF0000u);
    l23 = pack_bf16x2(w.z - hz, w.w - hw);
}
#define CP16(dst, src) \
    asm volatile("cp.async.cg.shared.global [%0], [%1], 16;" \
                 :: "r"(dst), "l"(src) : "memory")
#define CP_COMMIT() asm volatile("cp.async.commit_group;" ::: "memory")
#define CP_WAIT4()  asm volatile("cp.async.wait_group 4;" ::: "memory")
#define CP_WAIT0()  asm volatile("cp.async.wait_group 0;" ::: "memory")

// ------- Main kernel: m32/warp, smem B, 5-stage cp.async A ring (4 in flight)
__global__ void __launch_bounds__(NTHR, 3)
main_kernel(const float* __restrict__ W,
            const float* __restrict__ X,
            float* __restrict__ out) {
    extern __shared__ __align__(16) unsigned int smem[];
    unsigned int* sB = smem;                       // B frags [0, 30720)

    int tid = threadIdx.x, wid = tid >> 5, lane = tid & 31;
    int g = lane >> 2, t = lane & 3;
    int vbase = blockIdx.x * V_CTA;

    // 4 fragment row-groups per warp: g, g+8 (tile0), g+16, g+24 (tile1)
    const float* wp[4];
    #pragma unroll
    for (int i = 0; i < 4; i++) {
        int r = min(vbase + wid * 32 + g + 8 * i, Vq - 1);
        wp[i] = W + (size_t)r * Cq + 4 * t;
    }

    // ring: stage s holds kstep chunk; thread owns 4x16B, self-produced
    uint32_t ring = (uint32_t)__cvta_generic_to_shared(smem) + RING_OFF;
    uint32_t myoff = (uint32_t)((wid * 32 + g) * 64 + t * 16);

    // prologue: fill all 5 stages (ksteps 0..4), one group per stage
    #pragma unroll
    for (int ks = 0; ks < STAGES; ks++) {
        uint32_t dst = ring + ks * CHUNK + myoff;
        CP16(dst,        wp[0] + ks * 16);
        CP16(dst + 512,  wp[1] + ks * 16);
        CP16(dst + 1024, wp[2] + ks * 16);
        CP16(dst + 1536, wp[3] + ks * 16);
        CP_COMMIT();
    }

    // Copy B fragments to smem (30720B); LDG latency overlaps the ring fills
    {
        const uint4* src = (const uint4*)g_bfrag;
        uint4* dst = (uint4*)sB;
        #pragma unroll
        for (int i = tid; i < SB_U32 / 4; i += NTHR) dst[i] = src[i];
    }
    __syncthreads();

    float d0[NT][4], d1[NT][4];
    #pragma unroll
    for (int nt = 0; nt < NT; nt++)
        #pragma unroll
        for (int r = 0; r < 4; r++) { d0[nt][r] = 0.0f; d1[nt][r] = 0.0f; }

    const char* smem_c = (const char*)smem;

    #pragma unroll
    for (int ks = 0; ks < KS; ks++) {
        CP_WAIT4();   // group for kstep ks complete (4 newer may be pending)
        const float4* a = (const float4*)(smem_c + RING_OFF +
                                          (ks % STAGES) * CHUNK + myoff);
        float4 wa0 = a[0];
        float4 wa1 = a[32];
        float4 wa2 = a[64];
        float4 wa3 = a[96];

        // refill this stage with kstep ks+5; commit every iter (group count)
        if (ks + STAGES < KS) {
            uint32_t dst = ring + (ks % STAGES) * CHUNK + myoff;
            CP16(dst,        wp[0] + (ks + STAGES) * 16);
            CP16(dst + 512,  wp[1] + (ks + STAGES) * 16);
            CP16(dst + 1024, wp[2] + (ks + STAGES) * 16);
            CP16(dst + 1536, wp[3] + (ks + STAGES) * 16);
        }
        CP_COMMIT();

        uint32_t ah0[4], al0[4], ah1[4], al1[4];
        split4(wa0, ah0[0], ah0[2], al0[0], al0[2]);
        split4(wa1, ah0[1], ah0[3], al0[1], al0[3]);
        split4(wa2, ah1[0], ah1[2], al1[0], al1[2]);
        split4(wa3, ah1[1], ah1[3], al1[1], al1[3]);

        // B fragments from smem
        uint4 bb[NT];
        #pragma unroll
        for (int nt = 0; nt < NT; nt++)
            bb[nt] = *(const uint4*)&sB[((ks * NT + nt) * 32 + lane) * 4];

        #pragma unroll
        for (int nt = 0; nt < NT; nt++) {          // pass 0: hi*hi
            mma16816(d0[nt], ah0, bb[nt].x, bb[nt].y);
            mma16816(d1[nt], ah1, bb[nt].x, bb[nt].y);
        }
        #pragma unroll
        for (int nt = 0; nt < NT; nt++) {          // pass 1: hi*lo
            mma16816(d0[nt], ah0, bb[nt].z, bb[nt].w);
            mma16816(d1[nt], ah1, bb[nt].z, bb[nt].w);
        }
        #pragma unroll
        for (int nt = 0; nt < NT; nt++) {          // pass 2: lo*hi
            mma16816(d0[nt], al0, bb[nt].x, bb[nt].y);
            mma16816(d1[nt], al1, bb[nt].x, bb[nt].y);
        }
    }

    CP_WAIT0();
    __syncthreads();   // ring dead; alias as D scratch [128][49]
    float* Dsm = (float*)(smem_c + RING_OFF);
    #pragma unroll
    for (int nt = 0; nt < NT; nt++) {
        int col = nt * 8 + 2 * t;
        int q0 = (wid * 32 + g) * 49;
        int q1 = (wid * 32 + g + 8) * 49;
        int q2 = (wid * 32 + g + 16) * 49;
        int q3 = (wid * 32 + g + 24) * 49;
        Dsm[q0 + col] = d0[nt][0]; Dsm[q0 + col + 1] = d0[nt][1];
        Dsm[q1 + col] = d0[nt][2]; Dsm[q1 + col + 1] = d0[nt][3];
        Dsm[q2 + col] = d1[nt][0]; Dsm[q2 + col + 1] = d1[nt][1];
        Dsm[q3 + col] = d1[nt][2]; Dsm[q3 + col + 1] = d1[nt][3];
    }
    __syncthreads();

    // Epilogue: thread tid owns vertex vbase+tid, all 4 batches
    int v = vbase + tid;
    if (v < Vq) {
        float m[12];
        #pragma unroll
        for (int b = 0; b < Bq; b++) {
            #pragma unroll
            for (int j = 0; j < 12; j++) m[j] = Dsm[tid * 49 + j * 4 + b];
            const float* xp = X + ((size_t)b * Vq + v) * 3;
            float x0 = xp[0], x1 = xp[1], x2 = xp[2];
            float* op = out + ((size_t)b * Vq + v) * 3;
            op[0] = m[9]  + m[0]*x0 + m[1]*x1 + m[2]*x2;
            op[1] = m[10] + m[3]*x0 + m[4]*x1 + m[5]*x2;
            op[2] = m[11] + m[6]*x0 + m[7]*x1 + m[8]*x2;
        }
    }
}

// ---------------- launch ----------------
extern "C" void kernel_launch(void* const* d_in, const int* in_sizes, int n_in,
                              void* d_out, int out_size) {
    const float* X   = (const float*)d_in[0];
    const float* Vn  = (const float*)d_in[1];
    const float* r6  = (const float*)d_in[2];
    const float* W   = (const float*)d_in[3];
    const int*   idx = (const int*)d_in[4];   // JAX x64-disabled: int64 -> int32
    float* out = (float*)d_out;

    precompute_kernel<<<(Bq * Cq + 127) / 128, 128>>>(X, Vn, r6, idx);

    cudaFuncSetAttribute(main_kernel,
                         cudaFuncAttributeMaxDynamicSharedMemorySize, SMEM_BYTES);
    int grid = (Vq + V_CTA - 1) / V_CTA;    // 391
    main_kernel<<<grid, NTHR, SMEM_BYTES>>>(W, X, out);
}

// round 15
// speedup vs baseline: 1.5690x; 1.1530x over previous
#include <cuda_runtime.h>
#include <cuda_bf16.h>
#include <cstdint>

#define Bq 4
#define Vq 50000
#define Cq 160
#define V_CTA 128         // vertices per CTA (4 warps x m32)
#define NTHR 128
#define KP 10             // kstep-pairs: 160 / 16 (each pair = 2 x k8 mma)
#define NT 6              // 48 / 8
#define SB_U32 (KP * NT * 32 * 4)     // 7680 u32 = 30720B (B tf32 frags)
#define SMEM_BYTES (SB_U32 * 4)       // D scratch (128*49*4=25088B) aliases

// B operand (G) in gmem as tf32 words:
// u32 [p][nt][lane][j], j=0..3: (mma0.b0, mma0.b1, mma1.b0, mma1.b1)
// k-mapping: thread t owns actual k = p*16 + 4t + j (j -> component).
__device__ __align__(16) unsigned int g_bfrag[SB_U32];

// ---------------- Precompute: G -> permuted tf32 .col B fragments -----------
__global__ void precompute_kernel(const float* __restrict__ X,
                                  const float* __restrict__ Vn,
                                  const float* __restrict__ r6,
                                  const int* __restrict__ idx) {
    int i = blockIdx.x * blockDim.x + threadIdx.x;
    if (i >= Bq * Cq) return;
    int b = i / Cq, c = i % Cq;

    const float* d6 = r6 + (size_t)(b * Cq + c) * 6;
    float a1x = d6[0], a1y = d6[1], a1z = d6[2];
    float a2x = d6[3], a2y = d6[4], a2z = d6[5];

    float n1 = fmaxf(sqrtf(a1x*a1x + a1y*a1y + a1z*a1z), 1e-8f);
    float b1x = a1x/n1, b1y = a1y/n1, b1z = a1z/n1;
    float dt = b1x*a2x + b1y*a2y + b1z*a2z;
    float px = a2x - dt*b1x, py = a2y - dt*b1y, pz = a2z - dt*b1z;
    float n2 = fmaxf(sqrtf(px*px + py*py + pz*pz), 1e-8f);
    float b2x = px/n2, b2y = py/n2, b2z = pz/n2;
    float b3x = b1y*b2z - b1z*b2y;
    float b3y = b1z*b2x - b1x*b2z;
    float b3z = b1x*b2y - b1y*b2x;

    float R[3][3] = {{b1x,b1y,b1z},{b2x,b2y,b2z},{b3x,b3y,b3z}};

    int vi = idx[c];
    vi = max(0, min(Vq - 1, vi));
    const float* xc = X + ((size_t)b * Vq + vi) * 3;
    float cen[3] = {xc[0], xc[1], xc[2]};
    const float* vn = Vn + (size_t)(b * Cq + c) * 3;

    float g[12];
    #pragma unroll
    for (int k = 0; k < 3; k++) {
        #pragma unroll
        for (int d = 0; d < 3; d++) g[k*3 + d] = R[k][d];
        g[9 + k] = cen[k] + vn[k]
                 - (R[k][0]*cen[0] + R[k][1]*cen[1] + R[k][2]*cen[2]);
    }

    // actual k = c: p = c>>4, klo = c&15; t = klo>>2, j = klo&3
    int p   = c >> 4, klo = c & 15;
    int t   = klo >> 2;
    int j   = klo & 3;

    #pragma unroll
    for (int jj = 0; jj < 12; jj++) {
        int n = jj * 4 + b;
        int lane = (n & 7) * 4 + t;
        int slot = ((p * NT + (n >> 3)) * 32 + lane) * 4 + j;
        uint32_t tv;
        asm("cvt.rna.tf32.f32 %0, %1;" : "=r"(tv) : "f"(g[jj]));
        g_bfrag[slot] = tv;
    }
}

// ---------------- helpers ----------------
__device__ __forceinline__ uint32_t f2tf32(float f) {
    uint32_t r;
    asm("cvt.rna.tf32.f32 %0, %1;" : "=r"(r) : "f"(f));
    return r;
}
__device__ __forceinline__ void mma1688(float* d,
                                        uint32_t a0, uint32_t a1,
                                        uint32_t a2, uint32_t a3,
                                        uint32_t b0, uint32_t b1) {
    asm("mma.sync.aligned.m16n8k8.row.col.f32.tf32.tf32.f32 "
        "{%0,%1,%2,%3}, {%4,%5,%6,%7}, {%8,%9}, {%0,%1,%2,%3};"
        : "+f"(d[0]), "+f"(d[1]), "+f"(d[2]), "+f"(d[3])
        : "r"(a0), "r"(a1), "r"(a2), "r"(a3), "r"(b0), "r"(b1));
}

// ---------------- Main kernel: m32/warp, 1xTF32 ----------------
__global__ void __launch_bounds__(NTHR, 3)
main_kernel(const float* __restrict__ W,
            const float* __restrict__ X,
            float* __restrict__ out) {
    extern __shared__ __align__(16) unsigned int smem[];
    unsigned int* sB = smem;

    int tid = threadIdx.x, wid = tid >> 5, lane = tid & 31;
    int g = lane >> 2, t = lane & 3;
    int vbase = blockIdx.x * V_CTA;

    // 4 fragment row-groups per warp: g, g+8 (tile0), g+16, g+24 (tile1)
    const float* wp[4];
    #pragma unroll
    for (int i = 0; i < 4; i++) {
        int r = min(vbase + wid * 32 + g + 8 * i, Vq - 1);
        wp[i] = W + (size_t)r * Cq + 4 * t;
    }

    // Prefetch kstep-pair 0
    float4 cur0 = *(const float4*)wp[0];
    float4 cur1 = *(const float4*)wp[1];
    float4 cur2 = *(const float4*)wp[2];
    float4 cur3 = *(const float4*)wp[3];

    // Copy B fragments to smem (30720B)
    {
        const uint4* src = (const uint4*)g_bfrag;
        uint4* dst = (uint4*)sB;
        #pragma unroll
        for (int i = tid; i < SB_U32 / 4; i += NTHR) dst[i] = src[i];
    }
    __syncthreads();

    float d0[NT][4], d1[NT][4];
    #pragma unroll
    for (int nt = 0; nt < NT; nt++)
        #pragma unroll
        for (int r = 0; r < 4; r++) { d0[nt][r] = 0.0f; d1[nt][r] = 0.0f; }

    #pragma unroll
    for (int p = 0; p < KP; p++) {
        float4 n0, n1, n2, n3;
        if (p + 1 < KP) {
            n0 = *(const float4*)(wp[0] + (p + 1) * 16);
            n1 = *(const float4*)(wp[1] + (p + 1) * 16);
            n2 = *(const float4*)(wp[2] + (p + 1) * 16);
            n3 = *(const float4*)(wp[3] + (p + 1) * 16);
        }
        // tf32-convert A operands (tile0: rows g/g+8; tile1: rows g+16/g+24)
        uint32_t t0x = f2tf32(cur0.x), t0y = f2tf32(cur0.y),
                 t0z = f2tf32(cur0.z), t0w = f2tf32(cur0.w);
        uint32_t t1x = f2tf32(cur1.x), t1y = f2tf32(cur1.y),
                 t1z = f2tf32(cur1.z), t1w = f2tf32(cur1.w);
        uint32_t t2x = f2tf32(cur2.x), t2y = f2tf32(cur2.y),
                 t2z = f2tf32(cur2.z), t2w = f2tf32(cur2.w);
        uint32_t t3x = f2tf32(cur3.x), t3y = f2tf32(cur3.y),
                 t3z = f2tf32(cur3.z), t3w = f2tf32(cur3.w);

        // B fragments for this pair
        uint4 bb[NT];
        #pragma unroll
        for (int nt = 0; nt < NT; nt++)
            bb[nt] = *(const uint4*)&sB[((p * NT + nt) * 32 + lane) * 4];

        #pragma unroll
        for (int nt = 0; nt < NT; nt++) {
            // mma0 (actual k = p*16 + 4t + {0,1})
            mma1688(d0[nt], t0x, t1x, t0y, t1y, bb[nt].x, bb[nt].y);
            mma1688(d1[nt], t2x, t3x, t2y, t3y, bb[nt].x, bb[nt].y);
            // mma1 (actual k = p*16 + 4t + {2,3})
            mma1688(d0[nt], t0z, t1z, t0w, t1w, bb[nt].z, bb[nt].w);
            mma1688(d1[nt], t2z, t3z, t2w, t3w, bb[nt].z, bb[nt].w);
        }
        cur0 = n0; cur1 = n1; cur2 = n2; cur3 = n3;
    }

    __syncthreads();   // done reading sB; reuse as D scratch [128][49]
    float* Dsm = (float*)sB;
    #pragma unroll
    for (int nt = 0; nt < NT; nt++) {
        int col = nt * 8 + 2 * t;
        int q0 = (wid * 32 + g) * 49;
        int q1 = (wid * 32 + g + 8) * 49;
        int q2 = (wid * 32 + g + 16) * 49;
        int q3 = (wid * 32 + g + 24) * 49;
        Dsm[q0 + col] = d0[nt][0]; Dsm[q0 + col + 1] = d0[nt][1];
        Dsm[q1 + col] = d0[nt][2]; Dsm[q1 + col + 1] = d0[nt][3];
        Dsm[q2 + col] = d1[nt][0]; Dsm[q2 + col + 1] = d1[nt][1];
        Dsm[q3 + col] = d1[nt][2]; Dsm[q3 + col + 1] = d1[nt][3];
    }
    __syncthreads();

    // Epilogue: thread tid owns vertex vbase+tid, all 4 batches
    int v = vbase + tid;
    if (v < Vq) {
        float m[12];
        #pragma unroll
        for (int b = 0; b < Bq; b++) {
            #pragma unroll
            for (int j = 0; j < 12; j++) m[j] = Dsm[tid * 49 + j * 4 + b];
            const float* xp = X + ((size_t)b * Vq + v) * 3;
            float x0 = xp[0], x1 = xp[1], x2 = xp[2];
            float* op = out + ((size_t)b * Vq + v) * 3;
            op[0] = m[9]  + m[0]*x0 + m[1]*x1 + m[2]*x2;
            op[1] = m[10] + m[3]*x0 + m[4]*x1 + m[5]*x2;
            op[2] = m[11] + m[6]*x0 + m[7]*x1 + m[8]*x2;
        }
    }
}

// ---------------- launch ----------------
extern "C" void kernel_launch(void* const* d_in, const int* in_sizes, int n_in,
                              void* d_out, int out_size) {
    const float* X   = (const float*)d_in[0];
    const float* Vn  = (const float*)d_in[1];
    const float* r6  = (const float*)d_in[2];
    const float* W   = (const float*)d_in[3];
    const int*   idx = (const int*)d_in[4];   // JAX x64-disabled: int64 -> int32
    float* out = (float*)d_out;

    precompute_kernel<<<(Bq * Cq + 127) / 128, 128>>>(X, Vn, r6, idx);

    cudaFuncSetAttribute(main_kernel,
                         cudaFuncAttributeMaxDynamicSharedMemorySize, SMEM_BYTES);
    int grid = (Vq + V_CTA - 1) / V_CTA;    // 391
    main_kernel<<<grid, NTHR, SMEM_BYTES>>>(W, X, out);
}